// round 16
// baseline (speedup 1.0000x reference)
#include <cuda_runtime.h>
#include <cstdint>

// Gated delta-rule recurrent attention, single step. B=128, H=16, Dk=Dv=128.
//
// Round-15 = round-14 (best profile: ncu 36.8us, DRAM 73.9%) with ONE knob
// changed: state stores use __stwt (write-through) instead of __stcs.
// Rationale: zero write reuse -> dirty-L2 allocation buys nothing; in the
// steady-state timed loop the deferred writebacks collide with the next
// iteration's read stream. Write-through drains the write stream
// continuously and keeps L2 clean for reads.
//
// Structure (converged): 8192 CTAs x 128 threads, 32-col slices, s[8] f4
// regs front-batched, algebra: out = decay*(q.s) + (q.k)*delta so pass 2 is
// a pure fma+store burst; 2 barriers, 1 reduce epoch. 8 CTAs/SM.

#define BH   2048
#define DK   128
#define DV   128

__global__ __launch_bounds__(128, 8)
void delta_cell_kernel(const float* __restrict__ q,
                       const float* __restrict__ k,
                       const float* __restrict__ v,
                       const float* __restrict__ g,
                       const float* __restrict__ beta,
                       const float* __restrict__ state_in,
                       float* __restrict__ out,
                       float* __restrict__ state_out)
{
    const int bid  = blockIdx.x;         // 0..8191
    const int bh   = bid >> 2;           // (b*H + h)
    const int cb   = bid & 3;            // column block: cols [cb*32, cb*32+32)
    const int tid  = threadIdx.x;
    const int c4   = tid & 7;            // float4 col within slice (0..7)
    const int rg   = tid >> 3;           // row group (0..15), rows 8rg..8rg+7
    const int warp = tid >> 5;           // 0..3
    const int lane = tid & 31;

    __shared__ float  ks[DK];
    __shared__ float  qs[DK];
    __shared__ float4 red_kv[4][8];      // k-dot partial per warp per c4
    __shared__ float4 red_qd[4][8];      // q-dot partial per warp per c4
    __shared__ float  red_qk[4];         // scalar q.k partial per warp

    const float4* __restrict__ st4 =
        (const float4*)(state_in  + (size_t)bh * DK * DV);
    float4* __restrict__ sto4 =
        (float4*)(state_out + (size_t)bh * DK * DV);
    const int colbase = cb * 8 + c4;     // float4 column in the 32-wide row

    // ---- Front-batched state loads (no dependency on k/q) ----
    float4 s[8];
#pragma unroll
    for (int j = 0; j < 8; ++j)
        s[j] = __ldcs(&st4[(rg * 8 + j) * 32 + colbase]);

    // Small tensors + k/q staging ride under the state-load latency.
    const float4 vt   = ((const float4*)(v + (size_t)bh * DV))[cb * 8 + c4];
    const float decay = expf(g[bh]);
    const float bet   = beta[bh];
    ks[tid] = k[bh * DK + tid];
    qs[tid] = q[bh * DK + tid];
    __syncthreads();

    // ---- Pass 1: k-dot, q-dot, and scalar q.k partials over the patch ----
    float4 kv = make_float4(0.f, 0.f, 0.f, 0.f);
    float4 qd = make_float4(0.f, 0.f, 0.f, 0.f);
    float  qk = 0.f;
#pragma unroll
    for (int j = 0; j < 8; ++j) {
        const int row = rg * 8 + j;
        const float kk = ks[row];
        const float qq = qs[row];
        kv.x = fmaf(s[j].x, kk, kv.x);
        kv.y = fmaf(s[j].y, kk, kv.y);
        kv.z = fmaf(s[j].z, kk, kv.z);
        kv.w = fmaf(s[j].w, kk, kv.w);
        qd.x = fmaf(s[j].x, qq, qd.x);
        qd.y = fmaf(s[j].y, qq, qd.y);
        qd.z = fmaf(s[j].z, qq, qd.z);
        qd.w = fmaf(s[j].w, qq, qd.w);
        qk   = fmaf(kk, qq, qk);        // c4-redundant; summed over rg below
    }
    // Collapse the 4 row-groups within the warp (lane xor 8/16 keeps c4).
#pragma unroll
    for (int m = 8; m <= 16; m <<= 1) {
        kv.x += __shfl_xor_sync(0xffffffffu, kv.x, m);
        kv.y += __shfl_xor_sync(0xffffffffu, kv.y, m);
        kv.z += __shfl_xor_sync(0xffffffffu, kv.z, m);
        kv.w += __shfl_xor_sync(0xffffffffu, kv.w, m);
        qd.x += __shfl_xor_sync(0xffffffffu, qd.x, m);
        qd.y += __shfl_xor_sync(0xffffffffu, qd.y, m);
        qd.z += __shfl_xor_sync(0xffffffffu, qd.z, m);
        qd.w += __shfl_xor_sync(0xffffffffu, qd.w, m);
        qk   += __shfl_xor_sync(0xffffffffu, qk, m);
    }
    if (lane < 8) {
        red_kv[warp][c4] = kv;
        red_qd[warp][c4] = qd;
        if (lane == 0) red_qk[warp] = qk;
    }
    __syncthreads();   // the ONLY reduction barrier

    // ---- Totals + delta (redundantly in every thread) ----
    float4 kvt = make_float4(0.f, 0.f, 0.f, 0.f);
    float4 qdt = make_float4(0.f, 0.f, 0.f, 0.f);
#pragma unroll
    for (int w = 0; w < 4; ++w) {
        const float4 a = red_kv[w][c4];
        const float4 b = red_qd[w][c4];
        kvt.x += a.x; kvt.y += a.y; kvt.z += a.z; kvt.w += a.w;
        qdt.x += b.x; qdt.y += b.y; qdt.z += b.z; qdt.w += b.w;
    }
    const float qkt = red_qk[0] + red_qk[1] + red_qk[2] + red_qk[3];

    // kv_mem = decay*(state.k); delta = (v - kv_mem)*beta
    float4 delta;
    delta.x = (vt.x - decay * kvt.x) * bet;
    delta.y = (vt.y - decay * kvt.y) * bet;
    delta.z = (vt.z - decay * kvt.z) * bet;
    delta.w = (vt.w - decay * kvt.w) * bet;

    // out = decay*(q.state) + (q.k)*delta  -- written before the store burst
    if (tid < 8) {
        float4 o;
        o.x = fmaf(decay, qdt.x, qkt * delta.x);
        o.y = fmaf(decay, qdt.y, qkt * delta.y);
        o.z = fmaf(decay, qdt.z, qkt * delta.z);
        o.w = fmaf(decay, qdt.w, qkt * delta.w);
        ((float4*)(out + (size_t)bh * DV))[cb * 8 + c4] = o;
    }

    // ---- Pass 2: pure write-through store burst ----
#pragma unroll
    for (int j = 0; j < 8; ++j) {
        const int row = rg * 8 + j;
        const float kk = ks[row];
        float4 sn;
        sn.x = fmaf(decay, s[j].x, kk * delta.x);
        sn.y = fmaf(decay, s[j].y, kk * delta.y);
        sn.z = fmaf(decay, s[j].z, kk * delta.z);
        sn.w = fmaf(decay, s[j].w, kk * delta.w);
        __stwt(&sto4[row * 32 + colbase], sn);
    }
}

extern "C" void kernel_launch(void* const* d_in, const int* in_sizes, int n_in,
                              void* d_out, int out_size)
{
    const float* q     = (const float*)d_in[0];  // (B,H,1,Dk)
    const float* k     = (const float*)d_in[1];  // (B,H,1,Dk)
    const float* v     = (const float*)d_in[2];  // (B,H,1,Dv)
    const float* g     = (const float*)d_in[3];  // (B,H,1)
    const float* beta  = (const float*)d_in[4];  // (B,H,1)
    const float* state = (const float*)d_in[5];  // (B,H,Dk,Dv)

    float* out       = (float*)d_out;            // first B*H*Dv floats
    float* state_out = out + (size_t)BH * DV;    // then B*H*Dk*Dv floats

    delta_cell_kernel<<<BH * 4, 128>>>(q, k, v, g, beta, state,
                                       out, state_out);
}

// round 17
// speedup vs baseline: 1.0510x; 1.0510x over previous
#include <cuda_runtime.h>
#include <cstdint>

// Gated delta-rule recurrent attention, single step. B=128, H=16, Dk=Dv=128.
//
// FINAL (= round-14, best measured: wall 43.5us, ncu 36.8us, DRAM 73.9%).
// Round-15's __stwt experiment regressed (46.2us) -> reverted to __stcs.
//
// Converged design, with the evidence that selected each piece:
//  * 8192 CTAs x 128 threads: one (b,h,32-col-slice) per CTA. CTA-level
//    phase interleaving was the only lever that raised DRAM% (r5: 63->71%).
//  * s[8] float4 register-resident patch, front-batched __ldcs loads:
//    MLP-8 per thread is the sweet spot (r6 MLP-4: 49%; r10 MLP-16: 71%).
//  * Algebraic epilogue: out = decay*(q.s) + (q.k)*delta, so the q-dot
//    shares pass 1's shuffle+barrier reduction and pass 2 is a pure
//    fma + __stcs store burst. 2 barriers, 1 reduce epoch (r14: best ncu).
//  * L2 write-back (default __stcs) beats write-through (r15 regression).
// Effective mixed R/W throughput ~6.2 TB/s -- the practical ceiling for a
// balanced 134MB-read + 134MB-write stream on this part.

#define BH   2048
#define DK   128
#define DV   128

__global__ __launch_bounds__(128, 8)
void delta_cell_kernel(const float* __restrict__ q,
                       const float* __restrict__ k,
                       const float* __restrict__ v,
                       const float* __restrict__ g,
                       const float* __restrict__ beta,
                       const float* __restrict__ state_in,
                       float* __restrict__ out,
                       float* __restrict__ state_out)
{
    const int bid  = blockIdx.x;         // 0..8191
    const int bh   = bid >> 2;           // (b*H + h)
    const int cb   = bid & 3;            // column block: cols [cb*32, cb*32+32)
    const int tid  = threadIdx.x;
    const int c4   = tid & 7;            // float4 col within slice (0..7)
    const int rg   = tid >> 3;           // row group (0..15), rows 8rg..8rg+7
    const int warp = tid >> 5;           // 0..3
    const int lane = tid & 31;

    __shared__ float  ks[DK];
    __shared__ float  qs[DK];
    __shared__ float4 red_kv[4][8];      // k-dot partial per warp per c4
    __shared__ float4 red_qd[4][8];      // q-dot partial per warp per c4
    __shared__ float  red_qk[4];         // scalar q.k partial per warp

    const float4* __restrict__ st4 =
        (const float4*)(state_in  + (size_t)bh * DK * DV);
    float4* __restrict__ sto4 =
        (float4*)(state_out + (size_t)bh * DK * DV);
    const int colbase = cb * 8 + c4;     // float4 column in the 32-wide row

    // ---- Front-batched state loads (no dependency on k/q) ----
    float4 s[8];
#pragma unroll
    for (int j = 0; j < 8; ++j)
        s[j] = __ldcs(&st4[(rg * 8 + j) * 32 + colbase]);

    // Small tensors + k/q staging ride under the state-load latency.
    const float4 vt   = ((const float4*)(v + (size_t)bh * DV))[cb * 8 + c4];
    const float decay = expf(g[bh]);
    const float bet   = beta[bh];
    ks[tid] = k[bh * DK + tid];
    qs[tid] = q[bh * DK + tid];
    __syncthreads();

    // ---- Pass 1: k-dot, q-dot, and scalar q.k partials over the patch ----
    float4 kv = make_float4(0.f, 0.f, 0.f, 0.f);
    float4 qd = make_float4(0.f, 0.f, 0.f, 0.f);
    float  qk = 0.f;
#pragma unroll
    for (int j = 0; j < 8; ++j) {
        const int row = rg * 8 + j;
        const float kk = ks[row];
        const float qq = qs[row];
        kv.x = fmaf(s[j].x, kk, kv.x);
        kv.y = fmaf(s[j].y, kk, kv.y);
        kv.z = fmaf(s[j].z, kk, kv.z);
        kv.w = fmaf(s[j].w, kk, kv.w);
        qd.x = fmaf(s[j].x, qq, qd.x);
        qd.y = fmaf(s[j].y, qq, qd.y);
        qd.z = fmaf(s[j].z, qq, qd.z);
        qd.w = fmaf(s[j].w, qq, qd.w);
        qk   = fmaf(kk, qq, qk);        // c4-redundant; summed over rg below
    }
    // Collapse the 4 row-groups within the warp (lane xor 8/16 keeps c4).
#pragma unroll
    for (int m = 8; m <= 16; m <<= 1) {
        kv.x += __shfl_xor_sync(0xffffffffu, kv.x, m);
        kv.y += __shfl_xor_sync(0xffffffffu, kv.y, m);
        kv.z += __shfl_xor_sync(0xffffffffu, kv.z, m);
        kv.w += __shfl_xor_sync(0xffffffffu, kv.w, m);
        qd.x += __shfl_xor_sync(0xffffffffu, qd.x, m);
        qd.y += __shfl_xor_sync(0xffffffffu, qd.y, m);
        qd.z += __shfl_xor_sync(0xffffffffu, qd.z, m);
        qd.w += __shfl_xor_sync(0xffffffffu, qd.w, m);
        qk   += __shfl_xor_sync(0xffffffffu, qk, m);
    }
    if (lane < 8) {
        red_kv[warp][c4] = kv;
        red_qd[warp][c4] = qd;
        if (lane == 0) red_qk[warp] = qk;
    }
    __syncthreads();   // the ONLY reduction barrier

    // ---- Totals + delta (redundantly in every thread) ----
    float4 kvt = make_float4(0.f, 0.f, 0.f, 0.f);
    float4 qdt = make_float4(0.f, 0.f, 0.f, 0.f);
#pragma unroll
    for (int w = 0; w < 4; ++w) {
        const float4 a = red_kv[w][c4];
        const float4 b = red_qd[w][c4];
        kvt.x += a.x; kvt.y += a.y; kvt.z += a.z; kvt.w += a.w;
        qdt.x += b.x; qdt.y += b.y; qdt.z += b.z; qdt.w += b.w;
    }
    const float qkt = red_qk[0] + red_qk[1] + red_qk[2] + red_qk[3];

    // kv_mem = decay*(state.k); delta = (v - kv_mem)*beta
    float4 delta;
    delta.x = (vt.x - decay * kvt.x) * bet;
    delta.y = (vt.y - decay * kvt.y) * bet;
    delta.z = (vt.z - decay * kvt.z) * bet;
    delta.w = (vt.w - decay * kvt.w) * bet;

    // out = decay*(q.state) + (q.k)*delta  -- written before the store burst
    if (tid < 8) {
        float4 o;
        o.x = fmaf(decay, qdt.x, qkt * delta.x);
        o.y = fmaf(decay, qdt.y, qkt * delta.y);
        o.z = fmaf(decay, qdt.z, qkt * delta.z);
        o.w = fmaf(decay, qdt.w, qkt * delta.w);
        ((float4*)(out + (size_t)bh * DV))[cb * 8 + c4] = o;
    }

    // ---- Pass 2: pure evict-first store burst ----
#pragma unroll
    for (int j = 0; j < 8; ++j) {
        const int row = rg * 8 + j;
        const float kk = ks[row];
        float4 sn;
        sn.x = fmaf(decay, s[j].x, kk * delta.x);
        sn.y = fmaf(decay, s[j].y, kk * delta.y);
        sn.z = fmaf(decay, s[j].z, kk * delta.z);
        sn.w = fmaf(decay, s[j].w, kk * delta.w);
        __stcs(&sto4[row * 32 + colbase], sn);
    }
}

extern "C" void kernel_launch(void* const* d_in, const int* in_sizes, int n_in,
                              void* d_out, int out_size)
{
    const float* q     = (const float*)d_in[0];  // (B,H,1,Dk)
    const float* k     = (const float*)d_in[1];  // (B,H,1,Dk)
    const float* v     = (const float*)d_in[2];  // (B,H,1,Dv)
    const float* g     = (const float*)d_in[3];  // (B,H,1)
    const float* beta  = (const float*)d_in[4];  // (B,H,1)
    const float* state = (const float*)d_in[5];  // (B,H,Dk,Dv)

    float* out       = (float*)d_out;            // first B*H*Dv floats
    float* state_out = out + (size_t)BH * DV;    // then B*H*Dk*Dv floats

    delta_cell_kernel<<<BH * 4, 128>>>(q, k, v, g, beta, state,
                                       out, state_out);
}